// round 1
// baseline (speedup 1.0000x reference)
#include <cuda_runtime.h>
#include <cstdint>
#include <cstddef>

// Problem constants
#define BB    2
#define SS    4096
#define HIDD  2048
#define HH    16
#define KVH   4
#define HDD   128
#define KP    1024
#define QK_SCALE 0.08838834764831843f   // 128^-0.5

// ---------------------------------------------------------------------------
// Scratch (device globals; no dynamic allocation allowed)
// ---------------------------------------------------------------------------
__device__ float g_qkv [(size_t)BB * SS * 3072];      // (b*S+s, 3072): q[0:2048] k[2048:2560] v[2560:3072]
__device__ float g_pk  [(size_t)BB * KVH * KP * HDD]; // (b,kv,k,d)
__device__ float g_pv  [(size_t)BB * KVH * KP * HDD];
__device__ float g_attn[(size_t)BB * SS * 2048];      // (b*S+s, h*128+d)

// ---------------------------------------------------------------------------
// Generic NN GEMM: C[M,N] = A[M,Kd] @ B[Kd,N] (+bias), fp32
// Tiles: BM=BN=128, BK=32, 256 threads, 8x8 register tile per thread.
// ---------------------------------------------------------------------------
__global__ __launch_bounds__(256) void gemm_nn(
    const float* __restrict__ A, const float* __restrict__ Bw,
    const float* __restrict__ bias, float* __restrict__ C,
    int Kd, int lda, int ldb, int ldc)
{
    __shared__ float As[32][133];   // [k][m], pad 133: store banks = (5*k + m) % 32, conflict-free
    __shared__ float Bs[32][128];   // [k][n]

    const int tid = threadIdx.x;
    const int m0 = blockIdx.y * 128;
    const int n0 = blockIdx.x * 128;
    const int ty = tid >> 4;        // 0..15 -> rows ty*8..+7
    const int tx = tid & 15;        // 0..15 -> cols tx*8..+7

    float acc[8][8];
#pragma unroll
    for (int i = 0; i < 8; i++)
#pragma unroll
        for (int j = 0; j < 8; j++) acc[i][j] = 0.0f;

    for (int kt = 0; kt < Kd; kt += 32) {
        // Load A tile 128x32 (coalesced 128B rows), stored transposed
#pragma unroll
        for (int p = 0; p < 16; p++) {
            int m  = p * 8 + (tid >> 5);
            int kc = tid & 31;
            As[kc][m] = A[(long)(m0 + m) * lda + kt + kc];
        }
        // Load B tile 32x128 (coalesced 512B rows)
#pragma unroll
        for (int p = 0; p < 16; p++) {
            int r = p * 2 + (tid >> 7);
            int j = tid & 127;
            Bs[r][j] = Bw[(long)(kt + r) * ldb + n0 + j];
        }
        __syncthreads();

#pragma unroll 8
        for (int kk = 0; kk < 32; kk++) {
            float a[8];
#pragma unroll
            for (int i = 0; i < 8; i++) a[i] = As[kk][ty * 8 + i];
            float4 b0 = *(const float4*)&Bs[kk][tx * 8];
            float4 b1 = *(const float4*)&Bs[kk][tx * 8 + 4];
            float bb[8] = {b0.x, b0.y, b0.z, b0.w, b1.x, b1.y, b1.z, b1.w};
#pragma unroll
            for (int i = 0; i < 8; i++)
#pragma unroll
                for (int j = 0; j < 8; j++) acc[i][j] += a[i] * bb[j];
        }
        __syncthreads();
    }

    float bv[8];
#pragma unroll
    for (int j = 0; j < 8; j++) bv[j] = bias ? bias[n0 + tx * 8 + j] : 0.0f;
#pragma unroll
    for (int i = 0; i < 8; i++)
#pragma unroll
        for (int j = 0; j < 8; j++)
            C[(long)(m0 + ty * 8 + i) * ldc + n0 + tx * 8 + j] = acc[i][j] + bv[j];
}

// ---------------------------------------------------------------------------
// In-place RoPE on q and k regions of g_qkv.
// out[d]     = x[d]*cos[d]     - x[d+64]*sin[d]        (d < 64)
// out[d+64]  = x[d+64]*cos[d+64] + x[d]*sin[d+64]
// ---------------------------------------------------------------------------
__global__ __launch_bounds__(256) void rope_kernel(
    const float* __restrict__ cosp, const float* __restrict__ sinp)
{
    long idx = (long)blockIdx.x * blockDim.x + threadIdx.x;
    const long total = (long)BB * SS * (HH + KVH) * 64;   // pairs
    if (idx >= total) return;
    int  d   = (int)(idx & 63);
    long t   = idx >> 6;
    int  hh  = (int)(t % (HH + KVH));
    long row = t / (HH + KVH);                            // b*S + s
    int  col = (hh < HH) ? hh * 128 + d : 2048 + (hh - HH) * 128 + d;

    float* base = &g_qkv[row * 3072];
    float x1 = base[col];
    float x2 = base[col + 64];
    float c1 = cosp[row * 128 + d],  c2 = cosp[row * 128 + d + 64];
    float s1 = sinp[row * 128 + d],  s2 = sinp[row * 128 + d + 64];
    base[col]      = x1 * c1 - x2 * s1;
    base[col + 64] = x2 * c2 + x1 * s2;
}

// ---------------------------------------------------------------------------
// pk/pv projection: C[1024,128] = E^T (or Fp^T) @ kslice (4096 x 128, strided)
// blockIdx.z encodes (sel, b, kv). BM=BN=64, BK=32, 256 threads, 4x4 tile.
// ---------------------------------------------------------------------------
__global__ __launch_bounds__(256) void gemm_tn_proj(
    const float* __restrict__ Emat, const float* __restrict__ Fmat)
{
    const int z   = blockIdx.z;
    const int sel = z >> 3;             // 0 -> pk (E,k), 1 -> pv (Fp,v)
    const int b   = (z & 7) >> 2;
    const int kv  = z & 3;

    const float* A  = sel ? Fmat : Emat;                                  // [4096][1024]
    const float* Bm = g_qkv + (size_t)b * SS * 3072 + 2048 + sel * 512 + kv * 128; // rows stride 3072
    float*       C  = (sel ? g_pv : g_pk) + (size_t)(b * KVH + kv) * KP * HDD;

    const int m0 = blockIdx.y * 64;
    const int n0 = blockIdx.x * 64;

    __shared__ float As[32][64];
    __shared__ float Bs[32][64];

    const int tid = threadIdx.x;
    const int ty  = tid >> 4;     // rows ty*4..+3 (of 64)
    const int tx  = tid & 15;     // cols tx + 16*c

    float acc[4][4] = {};
    for (int kt = 0; kt < SS; kt += 32) {
#pragma unroll
        for (int p = 0; p < 8; p++) {
            int i = p * 4 + (tid >> 6);
            int j = tid & 63;
            As[i][j] = A [(long)(kt + i) * KP   + m0 + j];
            Bs[i][j] = Bm[(long)(kt + i) * 3072 + n0 + j];
        }
        __syncthreads();
#pragma unroll 8
        for (int kk = 0; kk < 32; kk++) {
            float a[4], bb[4];
#pragma unroll
            for (int r = 0; r < 4; r++) a[r]  = As[kk][ty * 4 + r];
#pragma unroll
            for (int c = 0; c < 4; c++) bb[c] = Bs[kk][tx + 16 * c];
#pragma unroll
            for (int r = 0; r < 4; r++)
#pragma unroll
                for (int c = 0; c < 4; c++) acc[r][c] += a[r] * bb[c];
        }
        __syncthreads();
    }
#pragma unroll
    for (int r = 0; r < 4; r++)
#pragma unroll
        for (int c = 0; c < 4; c++)
            C[(long)(m0 + ty * 4 + r) * HDD + n0 + tx + 16 * c] = acc[r][c];
}

// ---------------------------------------------------------------------------
// Fused attention: per block = 32 queries of one (b,h).
//   Phase 1: S = (Q*scale) @ pk^T  -> smem (32x1024)
//   softmax in-place (per-warp rows), mask dropped (constant over k)
//   Phase 2: O = P @ pv, normalize by row-sum in epilogue
// Dynamic smem: Qs 16KB + Ss 128KB + Cs 64.5KB + Ls = 213,632 B
// ---------------------------------------------------------------------------
__global__ __launch_bounds__(256) void attn_kernel()
{
    extern __shared__ float sm[];
    float* Qs  = sm;                 // [32][128]
    float* Ssm = sm + 32 * 128;      // [32][1024]
    float* Cs  = Ssm + 32 * 1024;    // [128][129]  (pad 129 -> strided-col reads conflict-free)
    float* Ls  = Cs + 128 * 129;     // [32] reciprocal row sums

    const int tid = threadIdx.x;
    const int bh  = blockIdx.y;
    const int b   = bh >> 4;
    const int h   = bh & 15;
    const int kv  = h >> 2;
    const int s0  = blockIdx.x * 32;
    const int wy  = tid >> 5;        // warp id 0..7 -> rows wy*4..+3
    const int tx  = tid & 31;        // lane -> cols tx + 32*cc

    // Load Q tile, pre-scaled
    for (int i = tid; i < 32 * 128; i += 256) {
        int r = i >> 7, d = i & 127;
        Qs[i] = g_qkv[((size_t)(b * SS + s0 + r)) * 3072 + h * 128 + d] * QK_SCALE;
    }
    const float* pkb = g_pk + (size_t)(b * KVH + kv) * KP * HDD;
    const float* pvb = g_pv + (size_t)(b * KVH + kv) * KP * HDD;

    // ---- Phase 1: scores ----
    for (int c = 0; c < 8; c++) {
        __syncthreads();
        for (int i = tid; i < 128 * 128; i += 256) {
            int j = i >> 7, d = i & 127;
            Cs[j * 129 + d] = pkb[(size_t)(c * 128 + j) * 128 + d];
        }
        __syncthreads();
        float acc[4][4] = {};
        for (int d = 0; d < 128; d++) {
            float a[4], bb[4];
#pragma unroll
            for (int r = 0; r < 4; r++)  a[r]  = Qs[(wy * 4 + r) * 128 + d];
#pragma unroll
            for (int cc = 0; cc < 4; cc++) bb[cc] = Cs[(tx + 32 * cc) * 129 + d];
#pragma unroll
            for (int r = 0; r < 4; r++)
#pragma unroll
                for (int cc = 0; cc < 4; cc++) acc[r][cc] += a[r] * bb[cc];
        }
#pragma unroll
        for (int r = 0; r < 4; r++)
#pragma unroll
            for (int cc = 0; cc < 4; cc++)
                Ssm[(wy * 4 + r) * 1024 + c * 128 + tx + 32 * cc] = acc[r][cc];
    }
    __syncthreads();

    // ---- Softmax (warp wy owns rows wy*4..+3; those rows were written by this warp) ----
#pragma unroll
    for (int r = 0; r < 4; r++) {
        float* srow = Ssm + (wy * 4 + r) * 1024;
        float m = -1e30f;
        for (int i = tx; i < 1024; i += 32) m = fmaxf(m, srow[i]);
#pragma unroll
        for (int off = 16; off > 0; off >>= 1)
            m = fmaxf(m, __shfl_xor_sync(0xffffffffu, m, off));
        float l = 0.0f;
        for (int i = tx; i < 1024; i += 32) {
            float e = __expf(srow[i] - m);
            srow[i] = e;
            l += e;
        }
#pragma unroll
        for (int off = 16; off > 0; off >>= 1)
            l += __shfl_xor_sync(0xffffffffu, l, off);
        if (tx == 0) Ls[wy * 4 + r] = 1.0f / l;
    }

    // ---- Phase 2: O = P @ pv ----
    float o[4][4] = {};
    for (int c = 0; c < 8; c++) {
        __syncthreads();
        for (int i = tid; i < 128 * 128; i += 256) {
            int j = i >> 7, d = i & 127;
            Cs[j * 129 + d] = pvb[(size_t)(c * 128 + j) * 128 + d];
        }
        __syncthreads();
        for (int j = 0; j < 128; j++) {
            float a[4], bb[4];
#pragma unroll
            for (int r = 0; r < 4; r++)   a[r]  = Ssm[(wy * 4 + r) * 1024 + c * 128 + j];
#pragma unroll
            for (int cc = 0; cc < 4; cc++) bb[cc] = Cs[j * 129 + tx + 32 * cc];
#pragma unroll
            for (int r = 0; r < 4; r++)
#pragma unroll
                for (int cc = 0; cc < 4; cc++) o[r][cc] += a[r] * bb[cc];
        }
    }

#pragma unroll
    for (int r = 0; r < 4; r++) {
        float inv = Ls[wy * 4 + r];
#pragma unroll
        for (int cc = 0; cc < 4; cc++)
            g_attn[((size_t)(b * SS + s0 + wy * 4 + r)) * 2048 + h * 128 + tx + 32 * cc]
                = o[r][cc] * inv;
    }
}

// ---------------------------------------------------------------------------
// Host launcher (graph-capturable: kernel launches only)
// ---------------------------------------------------------------------------
extern "C" void kernel_launch(void* const* d_in, const int* in_sizes, int n_in,
                              void* d_out, int out_size)
{
    const float* hs   = (const float*)d_in[0];
    const float* cosp = (const float*)d_in[1];
    const float* sinp = (const float*)d_in[2];
    // d_in[3] attention_mask: constant over k -> softmax-invariant, unused
    const float* Wq   = (const float*)d_in[4];
    const float* bq   = (const float*)d_in[5];
    const float* Wk   = (const float*)d_in[6];
    const float* bk   = (const float*)d_in[7];
    const float* Wv   = (const float*)d_in[8];
    const float* bvp  = (const float*)d_in[9];
    const float* Wo   = (const float*)d_in[10];
    const float* E    = (const float*)d_in[11];
    const float* Fp   = (const float*)d_in[12];
    float* out = (float*)d_out;

    float *qkv, *attn;
    cudaGetSymbolAddress((void**)&qkv,  g_qkv);
    cudaGetSymbolAddress((void**)&attn, g_attn);

    const dim3 blk(256);

    // QKV projections into combined scratch (ldc = 3072)
    gemm_nn<<<dim3(16, 64), blk>>>(hs, Wq, bq,  qkv,        HIDD, HIDD, 2048, 3072);
    gemm_nn<<<dim3(4,  64), blk>>>(hs, Wk, bk,  qkv + 2048, HIDD, HIDD,  512, 3072);
    gemm_nn<<<dim3(4,  64), blk>>>(hs, Wv, bvp, qkv + 2560, HIDD, HIDD,  512, 3072);

    // In-place RoPE on q and k
    {
        long total  = (long)BB * SS * (HH + KVH) * 64;
        int  blocks = (int)((total + 255) / 256);
        rope_kernel<<<blocks, blk>>>(cosp, sinp);
    }

    // pk / pv projections (16 slices)
    gemm_tn_proj<<<dim3(2, 16, 16), blk>>>(E, Fp);

    // Fused attention
    {
        const int ATTN_SMEM = (32 * 128 + 32 * 1024 + 128 * 129 + 32) * 4;  // 213,632 B
        cudaFuncSetAttribute(attn_kernel,
                             cudaFuncAttributeMaxDynamicSharedMemorySize, ATTN_SMEM);
        attn_kernel<<<dim3(SS / 32, BB * HH), blk, ATTN_SMEM>>>();
    }

    // Output projection
    gemm_nn<<<dim3(16, 64), blk>>>(attn, Wo, nullptr, out, 2048, 2048, 2048, 2048);
}